// round 9
// baseline (speedup 1.0000x reference)
#include <cuda_runtime.h>
#include <cuda_bf16.h>
#include <math.h>

#define BB   64
#define SS   512
#define EE   128
#define HH   128
#define GG   512          // 4*H
#define FWW  6
#define WW   507          // S - FW + 1
#define MT   64           // windows per CTA (2 groups of 32)
#define NTHREADS 512
#define NTILES 8          // 8*64 >= 507
#define NCTAS (NTILES*BB) // 512 CTAs

#define W_BYTES (GG*EE*2)        // 131072: resident bf16 weight (w_ih, then w_hh)
#define A_ROWS  80               // emb tile rows (72 used) / h tiles (rows 0..63)
#define A_BYTES (A_ROWS*256)     // 20480
#define X_ROWS  72               // tokens w0..w0+71 (69 needed)
#define X_STRIDE 1040            // 512 bf16 + 16B pad
#define X_BYTES (X_ROWS*X_STRIDE)        // 74880
#define SMEM_F  (W_BYTES + A_BYTES + X_BYTES)   // 226432 <= 227KB

// Scratch (device globals: allocation is forbidden)
__device__ __align__(16) __nv_bfloat16 g_wih16[GG * EE];
__device__ __align__(16) __nv_bfloat16 g_whh16[GG * HH];
__device__ unsigned g_featu[BB * HH];   // order-encoded float, atomicMax pooling
__device__ unsigned g_done;             // CTA completion counter

// ---------------------------------------------------------------------------
__device__ __forceinline__ unsigned sptr(const void* p) {
    return (unsigned)__cvta_generic_to_shared(p);
}
__device__ __forceinline__ float tanha_(float x) {
    float y; asm("tanh.approx.f32 %0, %1;" : "=f"(y) : "f"(x)); return y;
}
__device__ __forceinline__ float sigm_(float x) {
    return fmaf(0.5f, tanha_(0.5f * x), 0.5f);
}
__device__ __forceinline__ unsigned encf_(float x) {
    unsigned u = __float_as_uint(x);
    return (u & 0x80000000u) ? ~u : (u | 0x80000000u);
}
__device__ __forceinline__ float decf_(unsigned k) {
    return __uint_as_float((k & 0x80000000u) ? (k & 0x7fffffffu) : ~k);
}
__device__ __forceinline__ void ldsm4(unsigned* r, unsigned addr) {
    asm volatile("ldmatrix.sync.aligned.m8n8.x4.shared.b16 {%0,%1,%2,%3}, [%4];"
                 : "=r"(r[0]), "=r"(r[1]), "=r"(r[2]), "=r"(r[3]) : "r"(addr));
}
__device__ __forceinline__ void mma_bf16(float* d, const unsigned* a, unsigned b0, unsigned b1) {
    asm("mma.sync.aligned.m16n8k16.row.col.f32.bf16.bf16.f32 "
        "{%0,%1,%2,%3},{%4,%5,%6,%7},{%8,%9},{%0,%1,%2,%3};"
        : "+f"(d[0]), "+f"(d[1]), "+f"(d[2]), "+f"(d[3])
        : "r"(a[0]), "r"(a[1]), "r"(a[2]), "r"(a[3]), "r"(b0), "r"(b1));
}
__device__ __forceinline__ unsigned packbf2(float lo, float hi) {
    __nv_bfloat162 p = __float22bfloat162_rn(make_float2(lo, hi));
    return *reinterpret_cast<unsigned*>(&p);
}
__device__ __forceinline__ float2 unpackbf2(unsigned u) {
    return __bfloat1622float2(*reinterpret_cast<__nv_bfloat162*>(&u));
}
__device__ __forceinline__ void barg(int grp) {   // per-group named barrier (256 thr)
    asm volatile("bar.sync %0, 256;" :: "r"(grp + 1) : "memory");
}

// ---------------------------------------------------------------------------
// Kernel 0: weights fp32 -> bf16; reset pool accumulators + counter
// ---------------------------------------------------------------------------
__global__ void prep_kernel(const float* __restrict__ w_ih, const float* __restrict__ w_hh) {
    int i = blockIdx.x * blockDim.x + threadIdx.x;
    if (i < GG * EE) {
        g_wih16[i] = __float2bfloat16(w_ih[i]);
        g_whh16[i] = __float2bfloat16(w_hh[i]);
    }
    if (i < BB * HH) g_featu[i] = 0u;
    if (i == 0) g_done = 0u;
}

// ---------------------------------------------------------------------------
// Stage a full 512x128 bf16 weight matrix into smem, 16B-chunk swizzled (512 thr)
// ---------------------------------------------------------------------------
__device__ __forceinline__ void stage_w(const __nv_bfloat16* __restrict__ src, char* w_sc, int tid) {
    const uint4* s = (const uint4*)src;
    uint4* d = (uint4*)w_sc;
    #pragma unroll
    for (int i = 0; i < 16; ++i) {
        int id  = i * 512 + tid;
        int gs  = id >> 11;
        int rem = id & 2047;
        int n   = rem >> 4;
        int c   = rem & 15;
        d[gs * 2048 + n * 16 + (c ^ (n & 7))] = s[id];
    }
}

// ---------------------------------------------------------------------------
// X pass: X[row0..row0+16*MTILES) = emb @ w_ih^T + bias  (store only r < X_ROWS)
// ---------------------------------------------------------------------------
template<int MTILES>
__device__ __forceinline__ void xpass(unsigned aS, unsigned bB, char* x_sc, int row0,
                                      const float (&bias)[4][2][2],
                                      int g, int tq, int rs, int qb, int qh, int nw0) {
    float acc[4][MTILES][2][4];
    #pragma unroll
    for (int gs = 0; gs < 4; ++gs)
        #pragma unroll
        for (int mt = 0; mt < MTILES; ++mt)
            #pragma unroll
            for (int nt = 0; nt < 2; ++nt) {
                acc[gs][mt][nt][0] = bias[gs][nt][0]; acc[gs][mt][nt][1] = bias[gs][nt][1];
                acc[gs][mt][nt][2] = bias[gs][nt][0]; acc[gs][mt][nt][3] = bias[gs][nt][1];
            }
    unsigned aP = aS + (row0 + rs + 8 * qb) * 256;
    #pragma unroll
    for (int ks = 0; ks < 8; ++ks) {
        unsigned af[MTILES][4];
        unsigned ca = ((unsigned)((2 * ks + qh) ^ rs)) << 4;
        #pragma unroll
        for (int mt = 0; mt < MTILES; ++mt) ldsm4(af[mt], aP + mt * 4096 + ca);
        unsigned cb = ((unsigned)((2 * ks + qb) ^ rs)) << 4;
        #pragma unroll
        for (int gs = 0; gs < 4; ++gs) {
            unsigned bf[4];
            ldsm4(bf, bB + gs * 32768 + cb);
            #pragma unroll
            for (int mt = 0; mt < MTILES; ++mt) {
                mma_bf16(acc[gs][mt][0], af[mt], bf[0], bf[1]);
                mma_bf16(acc[gs][mt][1], af[mt], bf[2], bf[3]);
            }
        }
    }
    #pragma unroll
    for (int gs = 0; gs < 4; ++gs)
        #pragma unroll
        for (int mt = 0; mt < MTILES; ++mt)
            #pragma unroll
            for (int hh = 0; hh < 2; ++hh) {
                int r = row0 + mt * 16 + g + 8 * hh;
                if (r < X_ROWS) {
                    char* xr = x_sc + r * X_STRIDE;
                    #pragma unroll
                    for (int nt = 0; nt < 2; ++nt)
                        *(unsigned*)(xr + (gs * 128 + nw0 + nt * 8 + 2 * tq) * 2) =
                            packbf2(acc[gs][mt][nt][2 * hh], acc[gs][mt][nt][2 * hh + 1]);
                }
            }
}

// ---------------------------------------------------------------------------
// Load X rows [row0..row0+32) into accumulators
// ---------------------------------------------------------------------------
__device__ __forceinline__ void load_x(const char* x_sc, int row0, int g, int tq, int nw0,
                                       float (&acc)[4][2][2][4]) {
    #pragma unroll
    for (int mt = 0; mt < 2; ++mt)
        #pragma unroll
        for (int hh = 0; hh < 2; ++hh) {
            const char* xr = x_sc + (row0 + mt * 16 + g + 8 * hh) * X_STRIDE;
            #pragma unroll
            for (int gs = 0; gs < 4; ++gs)
                #pragma unroll
                for (int nt = 0; nt < 2; ++nt) {
                    unsigned u = *(const unsigned*)(xr + (gs * 128 + nw0 + nt * 8 + 2 * tq) * 2);
                    float2 v = unpackbf2(u);
                    acc[gs][mt][nt][2 * hh]     = v.x;
                    acc[gs][mt][nt][2 * hh + 1] = v.y;
                }
        }
}

// ---------------------------------------------------------------------------
// 32-row GEMM: acc += h_tile @ w_hh^T
// ---------------------------------------------------------------------------
__device__ __forceinline__ void gemm32(unsigned aH0, unsigned aH1, unsigned bB,
                                       int rs, int qb, int qh, float (&acc)[4][2][2][4]) {
    #pragma unroll
    for (int ks = 0; ks < 8; ++ks) {
        unsigned af0[4], af1[4];
        unsigned ca = ((unsigned)((2 * ks + qh) ^ rs)) << 4;
        ldsm4(af0, aH0 + ca);
        ldsm4(af1, aH1 + ca);
        unsigned cb = ((unsigned)((2 * ks + qb) ^ rs)) << 4;
        #pragma unroll
        for (int gs = 0; gs < 4; ++gs) {
            unsigned bf[4];
            ldsm4(bf, bB + gs * 32768 + cb);
            mma_bf16(acc[gs][0][0], af0, bf[0], bf[1]);
            mma_bf16(acc[gs][0][1], af0, bf[2], bf[3]);
            mma_bf16(acc[gs][1][0], af1, bf[0], bf[1]);
            mma_bf16(acc[gs][1][1], af1, bf[2], bf[3]);
        }
    }
}

// ---------------------------------------------------------------------------
// LSTM cell: c,h from gate accumulators
// ---------------------------------------------------------------------------
__device__ __forceinline__ void cell(const float (&acc)[4][2][2][4],
                                     float (&c)[2][2][4], float (&h)[2][2][4]) {
    #pragma unroll
    for (int mt = 0; mt < 2; ++mt)
        #pragma unroll
        for (int nt = 0; nt < 2; ++nt)
            #pragma unroll
            for (int q = 0; q < 4; ++q) {
                float gi = acc[0][mt][nt][q], gf = acc[1][mt][nt][q];
                float gg = acc[2][mt][nt][q], go = acc[3][mt][nt][q];
                float cn = sigm_(gf) * c[mt][nt][q] + sigm_(gi) * tanha_(gg);
                c[mt][nt][q] = cn;
                h[mt][nt][q] = sigm_(go) * tanha_(cn);
            }
}

// ---------------------------------------------------------------------------
// Fused kernel: X in smem, 6-step LSTM (2 independent warp groups), pool + FC
// ---------------------------------------------------------------------------
__global__ __launch_bounds__(NTHREADS, 1)
void lstm_kernel(const int* __restrict__ inputs,
                 const float* __restrict__ embed,
                 const float* __restrict__ b_ih,
                 const float* __restrict__ b_hh,
                 const float* __restrict__ fc_w,
                 const float* __restrict__ fc_b,
                 float* __restrict__ out)
{
    extern __shared__ char smem[];
    char* w_sc = smem;                       // weights (w_ih, then w_hh)
    char* a_sc = smem + W_BYTES;             // emb tile (80 rows) -> h tiles (rows 0..63)
    char* x_sc = smem + W_BYTES + A_BYTES;   // X: 72 rows

    const int tid  = threadIdx.x;
    const int grp  = tid >> 8;               // 0 or 1: independent 256-thread group
    const int gtid = tid & 255;
    const int lane = tid & 31;
    const int g    = lane >> 2;
    const int tq   = lane & 3;
    const int rs   = lane & 7;
    const int qb   = (lane >> 3) & 1;
    const int qh   = (lane >> 4) & 1;
    const int nw0  = (gtid >> 5) * 16;       // warp's 16-col slice per gate chunk

    const int b    = blockIdx.y;
    const int w0   = blockIdx.x * MT;
    const int wlim = WW - w0;                // valid local windows

    // ---- stage w_ih + gather embeddings (all 512 threads) ----
    stage_w(g_wih16, w_sc, tid);
    {
        // rows 0..63: 8 threads/row, 2 chunks each
        int r = tid >> 3, th = tid & 7;
        int tok = min(w0 + r, SS - 1);
        const float4* erow = (const float4*)(embed + (size_t)inputs[b * SS + tok] * EE);
        #pragma unroll
        for (int j = 0; j < 2; ++j) {
            int c = 2 * th + j;
            float4 v0 = erow[2 * c], v1 = erow[2 * c + 1];
            uint4 u;
            u.x = packbf2(v0.x, v0.y); u.y = packbf2(v0.z, v0.w);
            u.z = packbf2(v1.x, v1.y); u.w = packbf2(v1.z, v1.w);
            *(uint4*)(a_sc + r * 256 + ((c ^ (r & 7)) << 4)) = u;
        }
        // rows 64..79: 16 threads/row, 1 chunk each (threads 0..255)
        if (tid < 256) {
            int r2 = 64 + (tid >> 4), c2 = tid & 15;
            int tok2 = min(w0 + r2, SS - 1);
            const float4* erow2 = (const float4*)(embed + (size_t)inputs[b * SS + tok2] * EE);
            float4 v0 = erow2[2 * c2], v1 = erow2[2 * c2 + 1];
            uint4 u;
            u.x = packbf2(v0.x, v0.y); u.y = packbf2(v0.z, v0.w);
            u.z = packbf2(v1.x, v1.y); u.w = packbf2(v1.z, v1.w);
            *(uint4*)(a_sc + r2 * 256 + ((c2 ^ (r2 & 7)) << 4)) = u;
        }
    }

    // bias (hoisted; baked into X)
    float bias[4][2][2];
    #pragma unroll
    for (int gs = 0; gs < 4; ++gs)
        #pragma unroll
        for (int nt = 0; nt < 2; ++nt) {
            int col = gs * 128 + nw0 + nt * 8 + 2 * tq;
            float2 bi = *(const float2*)&b_ih[col];
            float2 bh = *(const float2*)&b_hh[col];
            bias[gs][nt][0] = bi.x + bh.x;
            bias[gs][nt][1] = bi.y + bh.y;
        }

    unsigned aS = sptr(a_sc), wS = sptr(w_sc);
    unsigned bB = wS + (nw0 + rs + 8 * qh) * 256;

    __syncthreads();   // emb + w_ih staged

    // ---- X = emb @ w_ih^T + bias (groups split the rows) ----
    if (grp == 0) {
        xpass<2>(aS, bB, x_sc, 0, bias, g, tq, rs, qb, qh, nw0);
    } else {
        xpass<2>(aS, bB, x_sc, 32, bias, g, tq, rs, qb, qh, nw0);
        xpass<1>(aS, bB, x_sc, 64, bias, g, tq, rs, qb, qh, nw0);
    }

    __syncthreads();              // X done; all w_ih + emb reads done
    stage_w(g_whh16, w_sc, tid);  // W := w_hh
    __syncthreads();              // w_hh visible

    // ---- recurrence: each group owns 32 windows, fully independent ----
    char* hbase = a_sc + grp * 8192;          // group's h tile (32 rows x 256B)
    unsigned aH0 = sptr(hbase) + (rs + 8 * qb) * 256;
    unsigned aH1 = aH0 + 4096;
    const int xrow0 = grp * 32;
    const int wrow0 = grp * 32;

    float acc[4][2][2][4];
    float c_st[2][2][4] = {};
    float hreg[2][2][4];
    float pmax[2][2] = {{-3.4e38f, -3.4e38f}, {-3.4e38f, -3.4e38f}};

    // t = 0: gates = X only
    load_x(x_sc, xrow0, g, tq, nw0, acc);
    cell(acc, c_st, hreg);
    #pragma unroll
    for (int mt = 0; mt < 2; ++mt)
        #pragma unroll
        for (int nt = 0; nt < 2; ++nt)
            #pragma unroll
            for (int hh = 0; hh < 2; ++hh) {
                int r   = mt * 16 + g + 8 * hh;
                int cb0 = (nw0 >> 3) + nt;
                *(unsigned*)(hbase + r * 256 + ((cb0 ^ g) << 4) + 4 * tq) =
                    packbf2(hreg[mt][nt][2 * hh], hreg[mt][nt][2 * hh + 1]);
            }
    barg(grp);   // h(0) visible to group

    for (int t = 1; t < FWW; ++t) {
        load_x(x_sc, xrow0 + t, g, tq, nw0, acc);
        gemm32(aH0, aH1, bB, rs, qb, qh, acc);   // reads h(t-1)
        cell(acc, c_st, hreg);
        if (t < FWW - 1) {
            barg(grp);   // all ldsm reads of h(t-1) complete
            #pragma unroll
            for (int mt = 0; mt < 2; ++mt)
                #pragma unroll
                for (int nt = 0; nt < 2; ++nt)
                    #pragma unroll
                    for (int hh = 0; hh < 2; ++hh) {
                        int r   = mt * 16 + g + 8 * hh;
                        int cb0 = (nw0 >> 3) + nt;
                        *(unsigned*)(hbase + r * 256 + ((cb0 ^ g) << 4) + 4 * tq) =
                            packbf2(hreg[mt][nt][2 * hh], hreg[mt][nt][2 * hh + 1]);
                    }
            barg(grp);   // h(t) visible
        } else {
            // final step: pool valid windows only
            #pragma unroll
            for (int mt = 0; mt < 2; ++mt)
                #pragma unroll
                for (int nt = 0; nt < 2; ++nt)
                    #pragma unroll
                    for (int hh = 0; hh < 2; ++hh) {
                        if (wrow0 + mt * 16 + g + 8 * hh < wlim) {
                            pmax[nt][0] = fmaxf(pmax[nt][0], hreg[mt][nt][2 * hh]);
                            pmax[nt][1] = fmaxf(pmax[nt][1], hreg[mt][nt][2 * hh + 1]);
                        }
                    }
        }
    }

    // ---- pool: reduce over rows (g, hh already folded) via shfl, atomicMax ----
    #pragma unroll
    for (int nt = 0; nt < 2; ++nt)
        #pragma unroll
        for (int e = 0; e < 2; ++e) {
            float m = pmax[nt][e];
            m = fmaxf(m, __shfl_xor_sync(0xffffffffu, m, 4));
            m = fmaxf(m, __shfl_xor_sync(0xffffffffu, m, 8));
            m = fmaxf(m, __shfl_xor_sync(0xffffffffu, m, 16));
            pmax[nt][e] = m;
        }
    if (g == 0) {
        #pragma unroll
        for (int nt = 0; nt < 2; ++nt)
            #pragma unroll
            for (int e = 0; e < 2; ++e)
                atomicMax(&g_featu[b * HH + nw0 + nt * 8 + 2 * tq + e], encf_(pmax[nt][e]));
    }

    // ---- last CTA computes the FC ----
    __threadfence();
    __shared__ unsigned s_last;
    if (tid == 0) {
        unsigned old = atomicAdd(&g_done, 1u);
        s_last = (old == (unsigned)(NCTAS - 1)) ? 1u : 0u;
    }
    __syncthreads();
    if (s_last && tid < 256) {
        int pair = tid >> 1;          // 0..127
        int fb   = pair >> 1;         // batch
        int o    = pair & 1;          // output class
        int kh   = tid & 1;           // k half
        float s = 0.0f;
        #pragma unroll 8
        for (int k = kh * 64; k < kh * 64 + 64; ++k) {
            unsigned enc = atomicAdd(&g_featu[fb * HH + k], 0u);   // coherent read
            s += decf_(enc) * fc_w[o * HH + k];
        }
        s += __shfl_xor_sync(0xffffffffu, s, 1);
        if (kh == 0) out[fb * 2 + o] = s + fc_b[o];
    }
}

// ---------------------------------------------------------------------------
extern "C" void kernel_launch(void* const* d_in, const int* in_sizes, int n_in,
                              void* d_out, int out_size)
{
    const int*   inputs = (const int*)  d_in[0];
    // d_in[1] = lengths : unused by the reference
    const float* embed  = (const float*)d_in[2];
    const float* w_ih   = (const float*)d_in[3];
    const float* w_hh   = (const float*)d_in[4];
    const float* b_ih   = (const float*)d_in[5];
    const float* b_hh   = (const float*)d_in[6];
    const float* fc_w   = (const float*)d_in[7];
    const float* fc_b   = (const float*)d_in[8];
    float* out = (float*)d_out;

    cudaFuncSetAttribute(lstm_kernel, cudaFuncAttributeMaxDynamicSharedMemorySize, SMEM_F);

    prep_kernel<<<(GG * EE + 255) / 256, 256>>>(w_ih, w_hh);
    lstm_kernel<<<dim3(NTILES, BB), NTHREADS, SMEM_F>>>(inputs, embed, b_ih, b_hh,
                                                        fc_w, fc_b, out);
}